// round 2
// baseline (speedup 1.0000x reference)
#include <cuda_runtime.h>

typedef unsigned long long u64;

#define NN 90
#define HD 128
#define NTHREADS 512
#define RPG 6            // rows per row-group: 16 groups * 6 = 96 (>= 90)

// smem layout (float offsets)
#define OFF_A 0          // 90*90   = 8100
#define OFF_H 8100       // 90*128  = 11520  (h0, then x)
#define OFF_R 19620      // 90*128            (r1)
#define OFF_T 31140      // 90*128            (A@h0 / A@x scratch)
#define SMEM_FLOATS 42660
// Yt (Y transposed, 128 x 91) overlays OFF_A..  (A and H are dead by then)
#define YT_LD 91

__device__ __forceinline__ u64 pack2(float a, float b) {
    u64 r; asm("mov.b64 %0, {%1, %2};" : "=l"(r) : "f"(a), "f"(b)); return r;
}
__device__ __forceinline__ void fma2(u64& d, u64 a, u64 b) {
    // packed fp32x2 FMA (Blackwell): 2 FMAs per instruction, fp32 rounding
    asm("fma.rn.f32x2 %0, %1, %2, %0;" : "+l"(d) : "l"(a), "l"(b));
}
__device__ __forceinline__ float2 unpack2(u64 v) {
    float lo, hi; asm("mov.b64 {%0, %1}, %2;" : "=f"(lo), "=f"(hi) : "l"(v));
    return make_float2(lo, hi);
}

// C[90 x 128] = S[90 x K] @ W[K x 128] (+ optional second product) (+bias)
// thread map: cg = tid&31 -> 4 consecutive cols; rg = tid>>5 -> 6 rows
template<int K, bool DUAL, bool RELU, bool ADDR, bool TROUT>
__device__ __forceinline__ void gemm_stage(
    const float* __restrict__ S,  int ldS,
    const float* __restrict__ S2, int ldS2,
    const float* __restrict__ W,            // [K][128] (global or smem)
    const float* __restrict__ W2,
    const float* __restrict__ bias,
    const float* __restrict__ bias2,
    const float* __restrict__ Radd,         // smem [90][128], added after relu
    float* __restrict__ outp)               // smem: stride 128, or Yt stride 91
{
    const int tid = threadIdx.x;
    const int cg = tid & 31;
    const int rg = tid >> 5;
    const int c0 = cg << 2;
    const int r0 = rg * RPG;

    float4 bz = make_float4(0.f, 0.f, 0.f, 0.f);
    if (bias) {
        bz = *(const float4*)(bias + c0);
        if (DUAL) {
            float4 b2 = *(const float4*)(bias2 + c0);
            bz.x += b2.x; bz.y += b2.y; bz.z += b2.z; bz.w += b2.w;
        }
    }
    u64 acc[RPG][2];
#pragma unroll
    for (int r = 0; r < RPG; ++r) {
        acc[r][0] = pack2(bz.x, bz.y);
        acc[r][1] = pack2(bz.z, bz.w);
    }

    // clamped per-row base pointers (rows >= 90 compute garbage but stay in-bounds)
    const float* srow[RPG];
    const float* srow2[RPG];
#pragma unroll
    for (int r = 0; r < RPG; ++r) {
        int rr = r0 + r; if (rr > NN - 1) rr = NN - 1;
        srow[r] = S + rr * ldS;
        if (DUAL) srow2[r] = S2 + rr * ldS2;
    }

    const ulonglong2* Wp  = (const ulonglong2*)W  + cg;   // row stride = 32 ull2
    const ulonglong2* W2p = DUAL ? ((const ulonglong2*)W2 + cg) : nullptr;

#pragma unroll 2
    for (int k = 0; k < K; ++k) {
        ulonglong2 wv = Wp[k * (HD / 4)];
        ulonglong2 wv2;
        if (DUAL) wv2 = W2p[k * (HD / 4)];
#pragma unroll
        for (int r = 0; r < RPG; ++r) {
            float s = srow[r][k];
            u64 ss = pack2(s, s);
            fma2(acc[r][0], ss, wv.x);
            fma2(acc[r][1], ss, wv.y);
            if (DUAL) {
                float s2 = srow2[r][k];
                u64 ss2 = pack2(s2, s2);
                fma2(acc[r][0], ss2, wv2.x);
                fma2(acc[r][1], ss2, wv2.y);
            }
        }
    }

#pragma unroll
    for (int r = 0; r < RPG; ++r) {
        int rr = r0 + r;
        if (rr < NN) {
            float2 p0 = unpack2(acc[r][0]);
            float2 p1 = unpack2(acc[r][1]);
            float v0 = p0.x, v1 = p0.y, v2 = p1.x, v3 = p1.y;
            if (RELU) {
                v0 = fmaxf(v0, 0.f); v1 = fmaxf(v1, 0.f);
                v2 = fmaxf(v2, 0.f); v3 = fmaxf(v3, 0.f);
            }
            if (ADDR) {
                float4 rv = *(const float4*)(Radd + rr * HD + c0);
                v0 += rv.x; v1 += rv.y; v2 += rv.z; v3 += rv.w;
            }
            if (TROUT) {
                outp[(c0 + 0) * YT_LD + rr] = v0;
                outp[(c0 + 1) * YT_LD + rr] = v1;
                outp[(c0 + 2) * YT_LD + rr] = v2;
                outp[(c0 + 3) * YT_LD + rr] = v3;
            } else {
                *(float4*)(outp + rr * HD + c0) = make_float4(v0, v1, v2, v3);
            }
        }
    }
}

__global__ void __launch_bounds__(NTHREADS, 1) graphcnn_kernel(
    const float* __restrict__ adj,
    const float* __restrict__ W0,  const float* __restrict__ b0,
    const float* __restrict__ W1,  const float* __restrict__ b1,
    const float* __restrict__ W2,  const float* __restrict__ b2,
    const float* __restrict__ Wr1, const float* __restrict__ br1,
    const float* __restrict__ Wr2, const float* __restrict__ br2,
    float* __restrict__ out)
{
    extern __shared__ float sm[];
    const int b = blockIdx.x;
    const int tid = threadIdx.x;

    // load adjacency tile: 8100 floats = 2025 float4 (aligned: 8100*4 % 16 == 0)
    {
        const float4* ag = (const float4*)(adj + (size_t)b * (NN * NN));
        float4* as = (float4*)(sm + OFF_A);
#pragma unroll
        for (int i = tid; i < (NN * NN) / 4; i += NTHREADS) as[i] = ag[i];
    }
    __syncthreads();

    // stage 1: h0 = A @ W0 + b0           (raw_x == I collapses first gconv)
    gemm_stage<NN, false, false, false, false>(
        sm + OFF_A, NN, nullptr, 0, W0, nullptr, b0, nullptr, nullptr, sm + OFF_H);
    __syncthreads();

    // stage 2: r1 = h0 @ Wr1 + br1
    gemm_stage<HD, false, false, false, false>(
        sm + OFF_H, HD, nullptr, 0, Wr1, nullptr, br1, nullptr, nullptr, sm + OFF_R);
    // stage 3a: T = A @ h0   (no hazard with stage 2: disjoint writes, shared reads)
    gemm_stage<NN, false, false, false, false>(
        sm + OFF_A, NN, nullptr, 0, sm + OFF_H, nullptr, nullptr, nullptr, nullptr, sm + OFF_T);
    __syncthreads();

    // stage 3b: x = relu(T @ W1 + b1) + r1   (overwrites h0)
    gemm_stage<HD, false, true, true, false>(
        sm + OFF_T, HD, nullptr, 0, W1, nullptr, b1, nullptr, sm + OFF_R, sm + OFF_H);
    __syncthreads();

    // stage 4a: T = A @ x
    gemm_stage<NN, false, false, false, false>(
        sm + OFF_A, NN, nullptr, 0, sm + OFF_H, nullptr, nullptr, nullptr, nullptr, sm + OFF_T);
    __syncthreads();

    // stage 4b: Yt = transpose( relu(T @ W2 + r1 @ Wr2 + b2 + br2) )
    //           Yt [128 x 91] overlays the (now dead) A / h0 region
    gemm_stage<HD, true, true, false, true>(
        sm + OFF_T, HD, sm + OFF_R, HD, W2, Wr2, b2, br2, nullptr, sm);
    __syncthreads();

    // stage 5: Z[i][j] = sum_c Yt[c][i] * Yt[c][j]
    const int lane = tid & 31;
    const int ig = tid >> 5;            // 16 i-groups * 6 rows
    const int i0 = ig * RPG;

    int irow[RPG];
#pragma unroll
    for (int r = 0; r < RPG; ++r) {
        int ii = i0 + r; if (ii > NN - 1) ii = NN - 1;
        irow[r] = ii;
    }

    u64 accp[RPG];                      // packed (j = lane, j = lane+32)
    float accs[RPG];                    // j = lane+64 (only lanes 0..25 valid)
#pragma unroll
    for (int r = 0; r < RPG; ++r) { accp[r] = 0ull; accs[r] = 0.f; }

    const bool has_j2 = (lane + 64) < NN;
#pragma unroll 2
    for (int c = 0; c < HD; ++c) {
        const float* yr = sm + c * YT_LD;
        float yj0 = yr[lane];
        float yj1 = yr[lane + 32];
        float yj2 = has_j2 ? yr[lane + 64] : 0.f;
        u64 yj01 = pack2(yj0, yj1);
#pragma unroll
        for (int r = 0; r < RPG; ++r) {
            float yi = yr[irow[r]];     // broadcast within warp
            fma2(accp[r], pack2(yi, yi), yj01);
            accs[r] = fmaf(yi, yj2, accs[r]);
        }
    }

    float* ob = out + (size_t)b * (NN * NN);
#pragma unroll
    for (int r = 0; r < RPG; ++r) {
        int ii = i0 + r;
        if (ii < NN) {
            float2 pj = unpack2(accp[r]);
            ob[ii * NN + lane]      = pj.x;
            ob[ii * NN + lane + 32] = pj.y;
            if (has_j2) ob[ii * NN + lane + 64] = accs[r];
        }
    }
}

extern "C" void kernel_launch(void* const* d_in, const int* in_sizes, int n_in,
                              void* d_out, int out_size) {
    const float* adj = (const float*)d_in[0];
    const float* W0  = (const float*)d_in[1];
    const float* b0  = (const float*)d_in[2];
    const float* W1  = (const float*)d_in[3];
    const float* b1  = (const float*)d_in[4];
    const float* W2  = (const float*)d_in[5];
    const float* b2  = (const float*)d_in[6];
    const float* Wr1 = (const float*)d_in[7];
    const float* br1 = (const float*)d_in[8];
    const float* Wr2 = (const float*)d_in[9];
    const float* br2 = (const float*)d_in[10];
    float* out = (float*)d_out;

    const int B = in_sizes[0] / (NN * NN);
    const size_t smem = SMEM_FLOATS * sizeof(float);   // 170,640 B < 227 KB

    cudaFuncSetAttribute(graphcnn_kernel,
                         cudaFuncAttributeMaxDynamicSharedMemorySize, (int)smem);
    graphcnn_kernel<<<B, NTHREADS, smem>>>(
        adj, W0, b0, W1, b1, W2, b2, Wr1, br1, Wr2, br2, out);
}

// round 3
// speedup vs baseline: 1.2597x; 1.2597x over previous
#include <cuda_runtime.h>

typedef unsigned long long u64;

#define NN 90
#define HD 128
#define NTHREADS 512
#define RPG 6            // rows per row-group: 16 groups * 6 = 96 (>= 90)

// smem layout (float offsets)
#define A_LD 92          // 90-float rows padded to 92 for 16B alignment
#define OFF_A 0          // 90*92  = 8280
#define OFF_H 8280       // 90*128 = 11520  (h0, then x)
#define OFF_R 19800      // 90*128          (r1)
#define OFF_T 31320      // 90*128          (A@h0 / A@x scratch)
#define OFF_Y 42840      // 90*132 = 11880  (Y row-major, padded)
#define Y_LD 132
#define SMEM_FLOATS 54720
// Yt (Y transposed, 128 x 91) overlays OFF_A.. (A and h0/x are dead by then)
#define YT_LD 91

__device__ __forceinline__ u64 pack2(float a, float b) {
    u64 r; asm("mov.b64 %0, {%1, %2};" : "=l"(r) : "f"(a), "f"(b)); return r;
}
__device__ __forceinline__ void fma2(u64& d, u64 a, u64 b) {
    asm("fma.rn.f32x2 %0, %1, %2, %0;" : "+l"(d) : "l"(a), "l"(b));
}
__device__ __forceinline__ float2 unpack2(u64 v) {
    float lo, hi; asm("mov.b64 {%0, %1}, %2;" : "=f"(lo), "=f"(hi) : "l"(v));
    return make_float2(lo, hi);
}

// C[90 x 128] = S[90 x K] @ W[K x 128] (+ optional second product) (+bias)
// thread map: cg = tid&31 -> 4 consecutive cols; rg = tid>>5 -> 6 rows
template<int K, bool DUAL, bool RELU, bool ADDR, bool TROUT>
__device__ __forceinline__ void gemm_stage(
    const float* __restrict__ S,  int ldS,
    const float* __restrict__ S2, int ldS2,
    const float* __restrict__ W,            // [K][128] (global or smem)
    const float* __restrict__ W2,
    const float* __restrict__ bias,
    const float* __restrict__ bias2,
    const float* __restrict__ Radd,         // smem [90][128], added after relu
    float* __restrict__ outp)               // smem stride 128; or TROUT: Yt@sm[0] + Y@OFF_Y
{
    const int tid = threadIdx.x;
    const int cg = tid & 31;
    const int rg = tid >> 5;
    const int c0 = cg << 2;
    const int r0 = rg * RPG;

    float4 bz = make_float4(0.f, 0.f, 0.f, 0.f);
    if (bias) {
        bz = *(const float4*)(bias + c0);
        if (DUAL) {
            float4 b2 = *(const float4*)(bias2 + c0);
            bz.x += b2.x; bz.y += b2.y; bz.z += b2.z; bz.w += b2.w;
        }
    }
    u64 acc[RPG][2];
#pragma unroll
    for (int r = 0; r < RPG; ++r) {
        acc[r][0] = pack2(bz.x, bz.y);
        acc[r][1] = pack2(bz.z, bz.w);
    }

    // clamped per-row base pointers (rows >= 90 compute garbage but stay in-bounds)
    const float* srow[RPG];
    const float* srow2[RPG];
#pragma unroll
    for (int r = 0; r < RPG; ++r) {
        int rr = r0 + r; if (rr > NN - 1) rr = NN - 1;
        srow[r] = S + rr * ldS;
        if (DUAL) srow2[r] = S2 + rr * ldS2;
    }

    const ulonglong2* Wp  = (const ulonglong2*)W  + cg;   // row stride = 32 ull2
    const ulonglong2* W2p = DUAL ? ((const ulonglong2*)W2 + cg) : nullptr;

    constexpr int KSTEP = DUAL ? 2 : 4;
    constexpr int K4 = (K / KSTEP) * KSTEP;

#pragma unroll 1
    for (int k = 0; k < K4; k += KSTEP) {
        ulonglong2 wv[KSTEP];
#pragma unroll
        for (int i = 0; i < KSTEP; ++i) wv[i] = Wp[(k + i) * (HD / 4)];

        if (!DUAL) {
            float4 s4[RPG];
#pragma unroll
            for (int r = 0; r < RPG; ++r)
                s4[r] = *(const float4*)(srow[r] + k);
#pragma unroll
            for (int i = 0; i < 4; ++i) {
#pragma unroll
                for (int r = 0; r < RPG; ++r) {
                    float s = ((const float*)&s4[r])[i];
                    u64 ss = pack2(s, s);
                    fma2(acc[r][0], ss, wv[i].x);
                    fma2(acc[r][1], ss, wv[i].y);
                }
            }
        } else {
            ulonglong2 wv2[KSTEP];
#pragma unroll
            for (int i = 0; i < KSTEP; ++i) wv2[i] = W2p[(k + i) * (HD / 4)];
            float2 sa[RPG], sb[RPG];
#pragma unroll
            for (int r = 0; r < RPG; ++r) {
                sa[r] = *(const float2*)(srow[r] + k);
                sb[r] = *(const float2*)(srow2[r] + k);
            }
#pragma unroll
            for (int i = 0; i < 2; ++i) {
#pragma unroll
                for (int r = 0; r < RPG; ++r) {
                    float s  = (i == 0) ? sa[r].x : sa[r].y;
                    float s2 = (i == 0) ? sb[r].x : sb[r].y;
                    u64 ss  = pack2(s, s);
                    u64 ss2 = pack2(s2, s2);
                    fma2(acc[r][0], ss,  wv[i].x);
                    fma2(acc[r][1], ss,  wv[i].y);
                    fma2(acc[r][0], ss2, wv2[i].x);
                    fma2(acc[r][1], ss2, wv2[i].y);
                }
            }
        }
    }
    // scalar tail (K=90 with KSTEP=4 -> k=88,89)
#pragma unroll
    for (int k = K4; k < K; ++k) {
        ulonglong2 wv = Wp[k * (HD / 4)];
#pragma unroll
        for (int r = 0; r < RPG; ++r) {
            float s = srow[r][k];
            u64 ss = pack2(s, s);
            fma2(acc[r][0], ss, wv.x);
            fma2(acc[r][1], ss, wv.y);
        }
    }

#pragma unroll
    for (int r = 0; r < RPG; ++r) {
        int rr = r0 + r;
        if (rr < NN) {
            float2 p0 = unpack2(acc[r][0]);
            float2 p1 = unpack2(acc[r][1]);
            float v0 = p0.x, v1 = p0.y, v2 = p1.x, v3 = p1.y;
            if (RELU) {
                v0 = fmaxf(v0, 0.f); v1 = fmaxf(v1, 0.f);
                v2 = fmaxf(v2, 0.f); v3 = fmaxf(v3, 0.f);
            }
            if (ADDR) {
                float4 rv = *(const float4*)(Radd + rr * HD + c0);
                v0 += rv.x; v1 += rv.y; v2 += rv.z; v3 += rv.w;
            }
            if (TROUT) {
                // Yt (stride 91) at sm[0]
                outp[(c0 + 0) * YT_LD + rr] = v0;
                outp[(c0 + 1) * YT_LD + rr] = v1;
                outp[(c0 + 2) * YT_LD + rr] = v2;
                outp[(c0 + 3) * YT_LD + rr] = v3;
                // Y row-major (stride 132) at OFF_Y
                *(float4*)(outp + OFF_Y + rr * Y_LD + c0) =
                    make_float4(v0, v1, v2, v3);
            } else {
                *(float4*)(outp + rr * HD + c0) = make_float4(v0, v1, v2, v3);
            }
        }
    }
}

__global__ void __launch_bounds__(NTHREADS, 1) graphcnn_kernel(
    const float* __restrict__ adj,
    const float* __restrict__ W0,  const float* __restrict__ b0,
    const float* __restrict__ W1,  const float* __restrict__ b1,
    const float* __restrict__ W2,  const float* __restrict__ b2,
    const float* __restrict__ Wr1, const float* __restrict__ br1,
    const float* __restrict__ Wr2, const float* __restrict__ br2,
    float* __restrict__ out)
{
    extern __shared__ float sm[];
    const int b = blockIdx.x;
    const int tid = threadIdx.x;

    // load adjacency into padded [90 x 92] smem tile
    {
        const float* ag = adj + (size_t)b * (NN * NN);
#pragma unroll
        for (int i = tid; i < NN * NN; i += NTHREADS) {
            int r = i / NN;
            int c = i - r * NN;
            sm[OFF_A + r * A_LD + c] = ag[i];
        }
    }
    __syncthreads();

    // stage 1: h0 = A @ W0 + b0           (raw_x == I collapses first gconv)
    gemm_stage<NN, false, false, false, false>(
        sm + OFF_A, A_LD, nullptr, 0, W0, nullptr, b0, nullptr, nullptr, sm + OFF_H);
    __syncthreads();

    // stage 2: r1 = h0 @ Wr1 + br1
    gemm_stage<HD, false, false, false, false>(
        sm + OFF_H, HD, nullptr, 0, Wr1, nullptr, br1, nullptr, nullptr, sm + OFF_R);
    // stage 3a: T = A @ h0   (no hazard with stage 2: disjoint writes, shared reads)
    gemm_stage<NN, false, false, false, false>(
        sm + OFF_A, A_LD, nullptr, 0, sm + OFF_H, nullptr, nullptr, nullptr, nullptr, sm + OFF_T);
    __syncthreads();

    // stage 3b: x = relu(T @ W1 + b1) + r1   (overwrites h0)
    gemm_stage<HD, false, true, true, false>(
        sm + OFF_T, HD, nullptr, 0, W1, nullptr, b1, nullptr, sm + OFF_R, sm + OFF_H);
    __syncthreads();

    // stage 4a: T = A @ x
    gemm_stage<NN, false, false, false, false>(
        sm + OFF_A, A_LD, nullptr, 0, sm + OFF_H, nullptr, nullptr, nullptr, nullptr, sm + OFF_T);
    __syncthreads();

    // stage 4b: Y = relu(T @ W2 + r1 @ Wr2 + b2 + br2), stored as Yt (overlays A/h0)
    //           AND row-major padded Y at OFF_Y
    gemm_stage<HD, true, true, false, true>(
        sm + OFF_T, HD, sm + OFF_R, HD, W2, Wr2, b2, br2, nullptr, sm);
    __syncthreads();

    // stage 5: Z[i][j] = sum_c Y[i][c] * Yt[c][j]
    const int lane = tid & 31;
    const int ig = tid >> 5;            // 16 i-groups * 6 rows
    const int i0 = ig * RPG;

    const float* yirow[RPG];
#pragma unroll
    for (int r = 0; r < RPG; ++r) {
        int ii = i0 + r; if (ii > NN - 1) ii = NN - 1;
        yirow[r] = sm + OFF_Y + ii * Y_LD;
    }

    u64 accp[RPG];                      // packed (j = lane, j = lane+32)
    float accs[RPG];                    // j = lane+64 (only lanes 0..25 valid)
#pragma unroll
    for (int r = 0; r < RPG; ++r) { accp[r] = 0ull; accs[r] = 0.f; }

    const bool has_j2 = (lane + 64) < NN;
#pragma unroll 1
    for (int c = 0; c < HD; c += 4) {
        float4 yi4[RPG];
#pragma unroll
        for (int r = 0; r < RPG; ++r)
            yi4[r] = *(const float4*)(yirow[r] + c);     // broadcast, 1 phase
#pragma unroll
        for (int cc = 0; cc < 4; ++cc) {
            const float* yr = sm + (c + cc) * YT_LD;
            float yj0 = yr[lane];
            float yj1 = yr[lane + 32];
            float yj2 = has_j2 ? yr[lane + 64] : 0.f;
            u64 yj01 = pack2(yj0, yj1);
#pragma unroll
            for (int r = 0; r < RPG; ++r) {
                float yi = ((const float*)&yi4[r])[cc];
                fma2(accp[r], pack2(yi, yi), yj01);
                accs[r] = fmaf(yi, yj2, accs[r]);
            }
        }
    }

    float* ob = out + (size_t)b * (NN * NN);
#pragma unroll
    for (int r = 0; r < RPG; ++r) {
        int ii = i0 + r;
        if (ii < NN) {
            float2 pj = unpack2(accp[r]);
            ob[ii * NN + lane]      = pj.x;
            ob[ii * NN + lane + 32] = pj.y;
            if (has_j2) ob[ii * NN + lane + 64] = accs[r];
        }
    }
}

extern "C" void kernel_launch(void* const* d_in, const int* in_sizes, int n_in,
                              void* d_out, int out_size) {
    const float* adj = (const float*)d_in[0];
    const float* W0  = (const float*)d_in[1];
    const float* b0  = (const float*)d_in[2];
    const float* W1  = (const float*)d_in[3];
    const float* b1  = (const float*)d_in[4];
    const float* W2  = (const float*)d_in[5];
    const float* b2  = (const float*)d_in[6];
    const float* Wr1 = (const float*)d_in[7];
    const float* br1 = (const float*)d_in[8];
    const float* Wr2 = (const float*)d_in[9];
    const float* br2 = (const float*)d_in[10];
    float* out = (float*)d_out;

    const int B = in_sizes[0] / (NN * NN);
    const size_t smem = SMEM_FLOATS * sizeof(float);   // 218,880 B < 227 KB

    cudaFuncSetAttribute(graphcnn_kernel,
                         cudaFuncAttributeMaxDynamicSharedMemorySize, (int)smem);
    graphcnn_kernel<<<B, NTHREADS, smem>>>(
        adj, W0, b0, W1, b1, W2, b2, Wr1, br1, Wr2, br2, out);
}

// round 4
// speedup vs baseline: 1.3785x; 1.0942x over previous
#include <cuda_runtime.h>

typedef unsigned long long u64;

#define NN 90
#define HD 128
#define NTHREADS 512
#define RPG 6            // rows per row-group: 16 groups * 6 = 96 (>= 90)

// smem layout (float offsets)
#define A_LD 92          // 90-float rows padded to 92 for 16B alignment
#define OFF_A 0          // 90*92  = 8280
#define OFF_H 8280       // 90*128 = 11520  (h0, then x)
#define OFF_R 19800      // 90*128          (r1)
#define OFF_T 31320      // 90*128          (A@h0 / A@x scratch)
#define OFF_Y 42840      // 90*132 = 11880  (G, then Y row-major, padded)
#define Y_LD 132
#define SMEM_FLOATS 54720
// Yt (Y transposed, 128 x 91) overlays OFF_A.. (A and h0/x are dead by then)
#define YT_LD 91

// ADDR modes
#define ADDR_NONE 0
#define ADDR_PRE  1      // v = relu(v + Radd)
#define ADDR_POST 2      // v = relu(v) + Radd

__device__ __forceinline__ u64 pack2(float a, float b) {
    u64 r; asm("mov.b64 %0, {%1, %2};" : "=l"(r) : "f"(a), "f"(b)); return r;
}
__device__ __forceinline__ void fma2(u64& d, u64 a, u64 b) {
    asm("fma.rn.f32x2 %0, %1, %2, %0;" : "+l"(d) : "l"(a), "l"(b));
}
__device__ __forceinline__ float2 unpack2(u64 v) {
    float lo, hi; asm("mov.b64 {%0, %1}, %2;" : "=f"(lo), "=f"(hi) : "l"(v));
    return make_float2(lo, hi);
}

// C[90 x 128] = S[90 x K] @ W[K x 128] + bias (+bias2) ; optional relu / residual
// thread map: cg = tid&31 -> 4 consecutive cols; rg = tid>>5 -> 6 rows
// W row stride is always 128 floats. W loads are double-buffer prefetched to
// hide L2 latency (~260cy) / smem latency.
template<int K, bool RELU, int ADDRM, bool TROUT>
__device__ __forceinline__ void gemm_stage(
    const float* __restrict__ S,  int ldS,
    const float* __restrict__ W,            // [K][128] (global or smem)
    const float* __restrict__ bias,
    const float* __restrict__ bias2,
    const float* __restrict__ Radd, int ldR,
    float* __restrict__ outp, int ldOut)    // TROUT: outp = sm base (Yt + Y)
{
    const int tid = threadIdx.x;
    const int cg = tid & 31;
    const int rg = tid >> 5;
    const int c0 = cg << 2;
    const int r0 = rg * RPG;

    float4 bz = make_float4(0.f, 0.f, 0.f, 0.f);
    if (bias) {
        bz = *(const float4*)(bias + c0);
        if (bias2) {
            float4 b2 = *(const float4*)(bias2 + c0);
            bz.x += b2.x; bz.y += b2.y; bz.z += b2.z; bz.w += b2.w;
        }
    }
    u64 acc[RPG][2];
#pragma unroll
    for (int r = 0; r < RPG; ++r) {
        acc[r][0] = pack2(bz.x, bz.y);
        acc[r][1] = pack2(bz.z, bz.w);
    }

    // clamped per-row base pointers (rows >= 90 compute garbage but stay in-bounds)
    const float* srow[RPG];
#pragma unroll
    for (int r = 0; r < RPG; ++r) {
        int rr = r0 + r; if (rr > NN - 1) rr = NN - 1;
        srow[r] = S + rr * ldS;
    }

    const ulonglong2* Wp = (const ulonglong2*)W + cg;   // row stride = 32 ull2

    constexpr int NITER = K / 4;
    constexpr int K4 = NITER * 4;

    ulonglong2 wv[2][4];
#pragma unroll
    for (int i = 0; i < 4; ++i) wv[0][i] = Wp[i * (HD / 4)];

#pragma unroll 2
    for (int it = 0; it < NITER; ++it) {
        const int k = it * 4;
        const int cur = it & 1;
        const int nxt = cur ^ 1;
        if (it + 1 < NITER) {
#pragma unroll
            for (int i = 0; i < 4; ++i)
                wv[nxt][i] = Wp[(k + 4 + i) * (HD / 4)];
        }
        float4 s4[RPG];
#pragma unroll
        for (int r = 0; r < RPG; ++r)
            s4[r] = *(const float4*)(srow[r] + k);
#pragma unroll
        for (int i = 0; i < 4; ++i) {
#pragma unroll
            for (int r = 0; r < RPG; ++r) {
                float s = ((const float*)&s4[r])[i];
                u64 ss = pack2(s, s);
                fma2(acc[r][0], ss, wv[cur][i].x);
                fma2(acc[r][1], ss, wv[cur][i].y);
            }
        }
    }
    // scalar tail (K=90 -> k=88,89)
#pragma unroll
    for (int k = K4; k < K; ++k) {
        ulonglong2 wvt = Wp[k * (HD / 4)];
#pragma unroll
        for (int r = 0; r < RPG; ++r) {
            float s = srow[r][k];
            u64 ss = pack2(s, s);
            fma2(acc[r][0], ss, wvt.x);
            fma2(acc[r][1], ss, wvt.y);
        }
    }

#pragma unroll
    for (int r = 0; r < RPG; ++r) {
        int rr = r0 + r;
        if (rr < NN) {
            float2 p0 = unpack2(acc[r][0]);
            float2 p1 = unpack2(acc[r][1]);
            float v0 = p0.x, v1 = p0.y, v2 = p1.x, v3 = p1.y;
            if (ADDRM == ADDR_PRE) {
                float4 rv = *(const float4*)(Radd + rr * ldR + c0);
                v0 += rv.x; v1 += rv.y; v2 += rv.z; v3 += rv.w;
            }
            if (RELU) {
                v0 = fmaxf(v0, 0.f); v1 = fmaxf(v1, 0.f);
                v2 = fmaxf(v2, 0.f); v3 = fmaxf(v3, 0.f);
            }
            if (ADDRM == ADDR_POST) {
                float4 rv = *(const float4*)(Radd + rr * ldR + c0);
                v0 += rv.x; v1 += rv.y; v2 += rv.z; v3 += rv.w;
            }
            if (TROUT) {
                // Yt (stride 91) at sm[0]
                outp[(c0 + 0) * YT_LD + rr] = v0;
                outp[(c0 + 1) * YT_LD + rr] = v1;
                outp[(c0 + 2) * YT_LD + rr] = v2;
                outp[(c0 + 3) * YT_LD + rr] = v3;
                // Y row-major (stride 132) at OFF_Y — exactly overwrites G that
                // this thread just consumed (same rr*Y_LD + c0 addresses)
                *(float4*)(outp + OFF_Y + rr * Y_LD + c0) =
                    make_float4(v0, v1, v2, v3);
            } else {
                *(float4*)(outp + rr * ldOut + c0) = make_float4(v0, v1, v2, v3);
            }
        }
    }
}

__global__ void __launch_bounds__(NTHREADS, 1) graphcnn_kernel(
    const float* __restrict__ adj,
    const float* __restrict__ W0,  const float* __restrict__ b0,
    const float* __restrict__ W1,  const float* __restrict__ b1,
    const float* __restrict__ W2,  const float* __restrict__ b2,
    const float* __restrict__ Wr1, const float* __restrict__ br1,
    const float* __restrict__ Wr2, const float* __restrict__ br2,
    float* __restrict__ out)
{
    extern __shared__ float sm[];
    const int b = blockIdx.x;
    const int tid = threadIdx.x;

    // load adjacency into padded [90 x 92] smem tile
    {
        const float* ag = adj + (size_t)b * (NN * NN);
#pragma unroll
        for (int i = tid; i < NN * NN; i += NTHREADS) {
            int r = i / NN;
            int c = i - r * NN;
            sm[OFF_A + r * A_LD + c] = ag[i];
        }
    }
    __syncthreads();

    // stage 1: h0 = A @ W0 + b0            (raw_x == I collapses first gconv)
    gemm_stage<NN, false, ADDR_NONE, false>(
        sm + OFF_A, A_LD, W0, b0, nullptr, nullptr, 0, sm + OFF_H, HD);
    __syncthreads();

    // stage 2: r1 = h0 @ Wr1 + br1
    gemm_stage<HD, false, ADDR_NONE, false>(
        sm + OFF_H, HD, Wr1, br1, nullptr, nullptr, 0, sm + OFF_R, HD);
    // stage 3a: T = A @ h0  (concurrent with stage 2: disjoint writes)
    gemm_stage<NN, false, ADDR_NONE, false>(
        sm + OFF_A, A_LD, sm + OFF_H, nullptr, nullptr, nullptr, 0, sm + OFF_T, HD);
    __syncthreads();

    // stage 3b: x = relu(T @ W1 + b1) + r1   (overwrites h0)
    gemm_stage<HD, true, ADDR_POST, false>(
        sm + OFF_T, HD, W1, b1, nullptr, sm + OFF_R, HD, sm + OFF_H, HD);
    __syncthreads();

    // stage 4a: T = A @ x
    gemm_stage<NN, false, ADDR_NONE, false>(
        sm + OFF_A, A_LD, sm + OFF_H, nullptr, nullptr, nullptr, 0, sm + OFF_T, HD);
    // stage 4b1: G = r1 @ Wr2 + br2 + b2  -> OFF_Y (stride 132), concurrent w/ 4a
    gemm_stage<HD, false, ADDR_NONE, false>(
        sm + OFF_R, HD, Wr2, br2, b2, nullptr, 0, sm + OFF_Y, Y_LD);
    __syncthreads();

    // stage 4b2: Y = relu(T @ W2 + G) -> Yt (overlays A/h0) + Y row-major @ OFF_Y
    gemm_stage<HD, true, ADDR_PRE, true>(
        sm + OFF_T, HD, W2, nullptr, nullptr, sm + OFF_Y, Y_LD, sm, 0);
    __syncthreads();

    // stage 5: Z[i][j] = sum_c Y[i][c] * Yt[c][j]
    const int lane = tid & 31;
    const int ig = tid >> 5;            // 16 i-groups * 6 rows
    const int i0 = ig * RPG;

    const float* yirow[RPG];
#pragma unroll
    for (int r = 0; r < RPG; ++r) {
        int ii = i0 + r; if (ii > NN - 1) ii = NN - 1;
        yirow[r] = sm + OFF_Y + ii * Y_LD;
    }

    u64 accp[RPG];                      // packed (j = lane, j = lane+32)
    float accs[RPG];                    // j = lane+64 (only lanes 0..25 valid)
#pragma unroll
    for (int r = 0; r < RPG; ++r) { accp[r] = 0ull; accs[r] = 0.f; }

    const bool has_j2 = (lane + 64) < NN;
#pragma unroll 1
    for (int c = 0; c < HD; c += 4) {
        float4 yi4[RPG];
#pragma unroll
        for (int r = 0; r < RPG; ++r)
            yi4[r] = *(const float4*)(yirow[r] + c);     // broadcast, 1 phase
#pragma unroll
        for (int cc = 0; cc < 4; ++cc) {
            const float* yr = sm + (c + cc) * YT_LD;
            float yj0 = yr[lane];
            float yj1 = yr[lane + 32];
            float yj2 = has_j2 ? yr[lane + 64] : 0.f;
            u64 yj01 = pack2(yj0, yj1);
#pragma unroll
            for (int r = 0; r < RPG; ++r) {
                float yi = ((const float*)&yi4[r])[cc];
                fma2(accp[r], pack2(yi, yi), yj01);
                accs[r] = fmaf(yi, yj2, accs[r]);
            }
        }
    }

    float* ob = out + (size_t)b * (NN * NN);
#pragma unroll
    for (int r = 0; r < RPG; ++r) {
        int ii = i0 + r;
        if (ii < NN) {
            float2 pj = unpack2(accp[r]);
            ob[ii * NN + lane]      = pj.x;
            ob[ii * NN + lane + 32] = pj.y;
            if (has_j2) ob[ii * NN + lane + 64] = accs[r];
        }
    }
}

extern "C" void kernel_launch(void* const* d_in, const int* in_sizes, int n_in,
                              void* d_out, int out_size) {
    const float* adj = (const float*)d_in[0];
    const float* W0  = (const float*)d_in[1];
    const float* b0  = (const float*)d_in[2];
    const float* W1  = (const float*)d_in[3];
    const float* b1  = (const float*)d_in[4];
    const float* W2  = (const float*)d_in[5];
    const float* b2  = (const float*)d_in[6];
    const float* Wr1 = (const float*)d_in[7];
    const float* br1 = (const float*)d_in[8];
    const float* Wr2 = (const float*)d_in[9];
    const float* br2 = (const float*)d_in[10];
    float* out = (float*)d_out;

    const int B = in_sizes[0] / (NN * NN);
    const size_t smem = SMEM_FLOATS * sizeof(float);   // 218,880 B

    cudaFuncSetAttribute(graphcnn_kernel,
                         cudaFuncAttributeMaxDynamicSharedMemorySize, (int)smem);
    graphcnn_kernel<<<B, NTHREADS, smem>>>(
        adj, W0, b0, W1, b1, W2, b2, Wr1, br1, Wr2, br2, out);
}

// round 5
// speedup vs baseline: 1.3814x; 1.0021x over previous
#include <cuda_runtime.h>

typedef unsigned long long u64;

#define NN 90
#define HD 128
#define NTHREADS 512
#define RPG 6            // rows per row-group: 16 groups * 6 = 96 (>= 90)

// smem layout (float offsets)
#define A_LD 92          // 90-float rows padded to 92 for 16B alignment
#define OFF_A 0          // 90*92  = 8280
#define OFF_H 8280       // 90*128 = 11520  (h0, then x)
#define OFF_R 19800      // 90*128          (r1)
#define OFF_T 31320      // 90*128          (A@h0 / A@x scratch)
#define OFF_Y 42840      // 90*132 = 11880  (G, then Y row-major, padded)
#define Y_LD 132
#define SMEM_FLOATS 54720
// Yt (Y transposed, 128 x 91) overlays OFF_A.. (A and h0/x are dead by then)
#define YT_LD 91

// ADDR modes
#define ADDR_NONE 0
#define ADDR_PRE  1      // v = relu(v + Radd)
#define ADDR_POST 2      // v = relu(v) + Radd

__device__ __forceinline__ u64 pack2(float a, float b) {
    u64 r; asm("mov.b64 %0, {%1, %2};" : "=l"(r) : "f"(a), "f"(b)); return r;
}
__device__ __forceinline__ void fma2(u64& d, u64 a, u64 b) {
    asm("fma.rn.f32x2 %0, %1, %2, %0;" : "+l"(d) : "l"(a), "l"(b));
}
__device__ __forceinline__ float2 unpack2(u64 v) {
    float lo, hi; asm("mov.b64 {%0, %1}, %2;" : "=f"(lo), "=f"(hi) : "l"(v));
    return make_float2(lo, hi);
}

// C[90 x 128] = S[90 x K] @ W[K x 128] + bias (+bias2) ; optional relu / residual
// thread map: cg = tid&31 -> 4 consecutive cols; rg = tid>>5 -> 6 rows
// W row stride is always 128 floats. W loads are double-buffer prefetched to
// hide L2 latency (~260cy) / smem latency.
template<int K, bool RELU, int ADDRM, bool TROUT>
__device__ __forceinline__ void gemm_stage(
    const float* __restrict__ S,  int ldS,
    const float* __restrict__ W,            // [K][128] (global or smem)
    const float* __restrict__ bias,
    const float* __restrict__ bias2,
    const float* __restrict__ Radd, int ldR,
    float* __restrict__ outp, int ldOut)    // TROUT: outp = sm base (Yt + Y)
{
    const int tid = threadIdx.x;
    const int cg = tid & 31;
    const int rg = tid >> 5;
    const int c0 = cg << 2;
    const int r0 = rg * RPG;

    float4 bz = make_float4(0.f, 0.f, 0.f, 0.f);
    if (bias) {
        bz = *(const float4*)(bias + c0);
        if (bias2) {
            float4 b2 = *(const float4*)(bias2 + c0);
            bz.x += b2.x; bz.y += b2.y; bz.z += b2.z; bz.w += b2.w;
        }
    }
    u64 acc[RPG][2];
#pragma unroll
    for (int r = 0; r < RPG; ++r) {
        acc[r][0] = pack2(bz.x, bz.y);
        acc[r][1] = pack2(bz.z, bz.w);
    }

    // clamped per-row base pointers (rows >= 90 compute garbage but stay in-bounds)
    const float* srow[RPG];
#pragma unroll
    for (int r = 0; r < RPG; ++r) {
        int rr = r0 + r; if (rr > NN - 1) rr = NN - 1;
        srow[r] = S + rr * ldS;
    }

    const ulonglong2* Wp = (const ulonglong2*)W + cg;   // row stride = 32 ull2

    constexpr int NITER = K / 4;
    constexpr int K4 = NITER * 4;

    ulonglong2 wv[2][4];
#pragma unroll
    for (int i = 0; i < 4; ++i) wv[0][i] = Wp[i * (HD / 4)];

#pragma unroll 2
    for (int it = 0; it < NITER; ++it) {
        const int k = it * 4;
        const int cur = it & 1;
        const int nxt = cur ^ 1;
        if (it + 1 < NITER) {
#pragma unroll
            for (int i = 0; i < 4; ++i)
                wv[nxt][i] = Wp[(k + 4 + i) * (HD / 4)];
        }
        float4 s4[RPG];
#pragma unroll
        for (int r = 0; r < RPG; ++r)
            s4[r] = *(const float4*)(srow[r] + k);
#pragma unroll
        for (int i = 0; i < 4; ++i) {
#pragma unroll
            for (int r = 0; r < RPG; ++r) {
                float s = ((const float*)&s4[r])[i];
                u64 ss = pack2(s, s);
                fma2(acc[r][0], ss, wv[cur][i].x);
                fma2(acc[r][1], ss, wv[cur][i].y);
            }
        }
    }
    // scalar tail (K=90 -> k=88,89)
#pragma unroll
    for (int k = K4; k < K; ++k) {
        ulonglong2 wvt = Wp[k * (HD / 4)];
#pragma unroll
        for (int r = 0; r < RPG; ++r) {
            float s = srow[r][k];
            u64 ss = pack2(s, s);
            fma2(acc[r][0], ss, wvt.x);
            fma2(acc[r][1], ss, wvt.y);
        }
    }

#pragma unroll
    for (int r = 0; r < RPG; ++r) {
        int rr = r0 + r;
        if (rr < NN) {
            float2 p0 = unpack2(acc[r][0]);
            float2 p1 = unpack2(acc[r][1]);
            float v0 = p0.x, v1 = p0.y, v2 = p1.x, v3 = p1.y;
            if (ADDRM == ADDR_PRE) {
                float4 rv = *(const float4*)(Radd + rr * ldR + c0);
                v0 += rv.x; v1 += rv.y; v2 += rv.z; v3 += rv.w;
            }
            if (RELU) {
                v0 = fmaxf(v0, 0.f); v1 = fmaxf(v1, 0.f);
                v2 = fmaxf(v2, 0.f); v3 = fmaxf(v3, 0.f);
            }
            if (ADDRM == ADDR_POST) {
                float4 rv = *(const float4*)(Radd + rr * ldR + c0);
                v0 += rv.x; v1 += rv.y; v2 += rv.z; v3 += rv.w;
            }
            if (TROUT) {
                // Yt (stride 91) at sm[0]
                outp[(c0 + 0) * YT_LD + rr] = v0;
                outp[(c0 + 1) * YT_LD + rr] = v1;
                outp[(c0 + 2) * YT_LD + rr] = v2;
                outp[(c0 + 3) * YT_LD + rr] = v3;
                // Y row-major (stride 132) at OFF_Y — exactly overwrites G that
                // this thread just consumed (same rr*Y_LD + c0 addresses)
                *(float4*)(outp + OFF_Y + rr * Y_LD + c0) =
                    make_float4(v0, v1, v2, v3);
            } else {
                *(float4*)(outp + rr * ldOut + c0) = make_float4(v0, v1, v2, v3);
            }
        }
    }
}

__global__ void __launch_bounds__(NTHREADS, 1) graphcnn_kernel(
    const float* __restrict__ adj,
    const float* __restrict__ W0,  const float* __restrict__ b0,
    const float* __restrict__ W1,  const float* __restrict__ b1,
    const float* __restrict__ W2,  const float* __restrict__ b2,
    const float* __restrict__ Wr1, const float* __restrict__ br1,
    const float* __restrict__ Wr2, const float* __restrict__ br2,
    float* __restrict__ out)
{
    extern __shared__ float sm[];
    const int b = blockIdx.x;
    const int tid = threadIdx.x;

    // load adjacency into padded [90 x 92] smem tile
    {
        const float* ag = adj + (size_t)b * (NN * NN);
#pragma unroll
        for (int i = tid; i < NN * NN; i += NTHREADS) {
            int r = i / NN;
            int c = i - r * NN;
            sm[OFF_A + r * A_LD + c] = ag[i];
        }
    }
    __syncthreads();

    // stage 1: h0 = A @ W0 + b0            (raw_x == I collapses first gconv)
    gemm_stage<NN, false, ADDR_NONE, false>(
        sm + OFF_A, A_LD, W0, b0, nullptr, nullptr, 0, sm + OFF_H, HD);
    __syncthreads();

    // stage 2: r1 = h0 @ Wr1 + br1
    gemm_stage<HD, false, ADDR_NONE, false>(
        sm + OFF_H, HD, Wr1, br1, nullptr, nullptr, 0, sm + OFF_R, HD);
    // stage 3a: T = A @ h0  (concurrent with stage 2: disjoint writes)
    gemm_stage<NN, false, ADDR_NONE, false>(
        sm + OFF_A, A_LD, sm + OFF_H, nullptr, nullptr, nullptr, 0, sm + OFF_T, HD);
    __syncthreads();

    // stage 3b: x = relu(T @ W1 + b1) + r1   (overwrites h0)
    gemm_stage<HD, true, ADDR_POST, false>(
        sm + OFF_T, HD, W1, b1, nullptr, sm + OFF_R, HD, sm + OFF_H, HD);
    __syncthreads();

    // stage 4a: T = A @ x
    gemm_stage<NN, false, ADDR_NONE, false>(
        sm + OFF_A, A_LD, sm + OFF_H, nullptr, nullptr, nullptr, 0, sm + OFF_T, HD);
    // stage 4b1: G = r1 @ Wr2 + br2 + b2  -> OFF_Y (stride 132), concurrent w/ 4a
    gemm_stage<HD, false, ADDR_NONE, false>(
        sm + OFF_R, HD, Wr2, br2, b2, nullptr, 0, sm + OFF_Y, Y_LD);
    __syncthreads();

    // stage 4b2: Y = relu(T @ W2 + G) -> Yt (overlays A/h0) + Y row-major @ OFF_Y
    gemm_stage<HD, true, ADDR_PRE, true>(
        sm + OFF_T, HD, W2, nullptr, nullptr, sm + OFF_Y, Y_LD, sm, 0);
    __syncthreads();

    // stage 5: Z[i][j] = sum_c Y[i][c] * Yt[c][j]
    const int lane = tid & 31;
    const int ig = tid >> 5;            // 16 i-groups * 6 rows
    const int i0 = ig * RPG;

    const float* yirow[RPG];
#pragma unroll
    for (int r = 0; r < RPG; ++r) {
        int ii = i0 + r; if (ii > NN - 1) ii = NN - 1;
        yirow[r] = sm + OFF_Y + ii * Y_LD;
    }

    u64 accp[RPG];                      // packed (j = lane, j = lane+32)
    float accs[RPG];                    // j = lane+64 (only lanes 0..25 valid)
#pragma unroll
    for (int r = 0; r < RPG; ++r) { accp[r] = 0ull; accs[r] = 0.f; }

    const bool has_j2 = (lane + 64) < NN;
#pragma unroll 1
    for (int c = 0; c < HD; c += 4) {
        float4 yi4[RPG];
#pragma unroll
        for (int r = 0; r < RPG; ++r)
            yi4[r] = *(const float4*)(yirow[r] + c);     // broadcast, 1 phase
#pragma unroll
        for (int cc = 0; cc < 4; ++cc) {
            const float* yr = sm + (c + cc) * YT_LD;
            float yj0 = yr[lane];
            float yj1 = yr[lane + 32];
            float yj2 = has_j2 ? yr[lane + 64] : 0.f;
            u64 yj01 = pack2(yj0, yj1);
#pragma unroll
            for (int r = 0; r < RPG; ++r) {
                float yi = ((const float*)&yi4[r])[cc];
                fma2(accp[r], pack2(yi, yi), yj01);
                accs[r] = fmaf(yi, yj2, accs[r]);
            }
        }
    }

    float* ob = out + (size_t)b * (NN * NN);
#pragma unroll
    for (int r = 0; r < RPG; ++r) {
        int ii = i0 + r;
        if (ii < NN) {
            float2 pj = unpack2(accp[r]);
            ob[ii * NN + lane]      = pj.x;
            ob[ii * NN + lane + 32] = pj.y;
            if (has_j2) ob[ii * NN + lane + 64] = accs[r];
        }
    }
}

extern "C" void kernel_launch(void* const* d_in, const int* in_sizes, int n_in,
                              void* d_out, int out_size) {
    const float* adj = (const float*)d_in[0];
    const float* W0  = (const float*)d_in[1];
    const float* b0  = (const float*)d_in[2];
    const float* W1  = (const float*)d_in[3];
    const float* b1  = (const float*)d_in[4];
    const float* W2  = (const float*)d_in[5];
    const float* b2  = (const float*)d_in[6];
    const float* Wr1 = (const float*)d_in[7];
    const float* br1 = (const float*)d_in[8];
    const float* Wr2 = (const float*)d_in[9];
    const float* br2 = (const float*)d_in[10];
    float* out = (float*)d_out;

    const int B = in_sizes[0] / (NN * NN);
    const size_t smem = SMEM_FLOATS * sizeof(float);   // 218,880 B

    cudaFuncSetAttribute(graphcnn_kernel,
                         cudaFuncAttributeMaxDynamicSharedMemorySize, (int)smem);
    graphcnn_kernel<<<B, NTHREADS, smem>>>(
        adj, W0, b0, W1, b1, W2, b2, Wr1, br1, Wr2, br2, out);
}

// round 6
// speedup vs baseline: 1.8647x; 1.3499x over previous
#include <cuda_runtime.h>

typedef unsigned long long u64;

#define NN 90
#define HD 128
#define NTHREADS 512
#define RPG 6            // rows per row-group: 16 groups * 6 = 96 (>= 90)

// smem layout (float offsets)
#define A_LD 92          // 90-float rows padded to 92 for 16B alignment
#define OFF_A  0         // 90*92  = 8280
#define OFF_AS 8280      // a[90] rowsums (pad to 96)
#define OFF_B1 8376      // 90*128 = 11520
#define OFF_B2 19896     // 90*128 = 11520
#define OFF_Y  31416     // 90*132 = 11880 (Y row-major, padded)
#define OFF_YT 43296     // 128*91 = 11648 (Y transposed)
#define SMEM_FLOATS 54944
#define Y_LD 132
#define YT_LD 91

// ---------------- precomputed weight products (device scratch) --------------
__device__ __align__(16) float g_U1[NN * HD];   // W0 @ Wr1
__device__ __align__(16) float g_V1[NN * HD];   // W0 @ W1
__device__ __align__(16) float g_P [NN * HD];   // U1 @ W2
__device__ __align__(16) float g_Q [NN * HD];   // U1 @ Wr2
__device__ __align__(16) float g_u1[HD];        // Wr1^T b0 + br1
__device__ __align__(16) float g_v1[HD];        // W1^T b0
__device__ __align__(16) float g_p [HD];        // W2^T u1
__device__ __align__(16) float g_q [HD];        // Wr2^T u1 + b2 + br2

// pre1: blocks 0,1 -> U1/u1 ; blocks 2,3 -> V1/v1
__global__ void pre1_kernel(const float* __restrict__ W0,
                            const float* __restrict__ Wr1,
                            const float* __restrict__ W1,
                            const float* __restrict__ b0,
                            const float* __restrict__ br1)
{
    const int half = blockIdx.x & 1;
    const bool doU = blockIdx.x < 2;
    const float* M = doU ? Wr1 : W1;            // [128][128]
    float* outM = doU ? g_U1 : g_V1;
    const int lo = half * (NN * HD / 2), hi = lo + NN * HD / 2;
    for (int idx = lo + threadIdx.x; idx < hi; idx += blockDim.x) {
        int i = idx / HD, j = idx - i * HD;
        float s = 0.f;
        for (int k = 0; k < HD; ++k) s = fmaf(W0[i * HD + k], M[k * HD + j], s);
        outM[idx] = s;
    }
    if (half == 0 && threadIdx.x < HD) {
        int j = threadIdx.x;
        float s = 0.f;
        for (int k = 0; k < HD; ++k) s = fmaf(b0[k], M[k * HD + j], s);
        if (doU) g_u1[j] = s + br1[j]; else g_v1[j] = s;
    }
}

// pre2: blocks 0,1 -> P/p ; blocks 2,3 -> Q/q     (needs g_U1/g_u1 from pre1)
__global__ void pre2_kernel(const float* __restrict__ W2,
                            const float* __restrict__ Wr2,
                            const float* __restrict__ b2,
                            const float* __restrict__ br2)
{
    const int half = blockIdx.x & 1;
    const bool doP = blockIdx.x < 2;
    const float* M = doP ? W2 : Wr2;            // [128][128]
    float* outM = doP ? g_P : g_Q;
    const int lo = half * (NN * HD / 2), hi = lo + NN * HD / 2;
    for (int idx = lo + threadIdx.x; idx < hi; idx += blockDim.x) {
        int i = idx / HD, j = idx - i * HD;
        float s = 0.f;
        for (int k = 0; k < HD; ++k) s = fmaf(g_U1[i * HD + k], M[k * HD + j], s);
        outM[idx] = s;
    }
    if (half == 0 && threadIdx.x < HD) {
        int j = threadIdx.x;
        float s = 0.f;
        for (int k = 0; k < HD; ++k) s = fmaf(g_u1[k], M[k * HD + j], s);
        if (doP) g_p[j] = s;
        else     g_q[j] = s + b2[j] + br2[j];
    }
}

// ---------------------------- packed fp32x2 helpers -------------------------
__device__ __forceinline__ u64 pack2(float a, float b) {
    u64 r; asm("mov.b64 %0, {%1, %2};" : "=l"(r) : "f"(a), "f"(b)); return r;
}
__device__ __forceinline__ void fma2(u64& d, u64 a, u64 b) {
    asm("fma.rn.f32x2 %0, %1, %2, %0;" : "+l"(d) : "l"(a), "l"(b));
}
__device__ __forceinline__ float2 unpack2(u64 v) {
    float lo, hi; asm("mov.b64 {%0, %1}, %2;" : "=f"(lo), "=f"(hi) : "l"(v));
    return make_float2(lo, hi);
}

// C[90 x 128] = S[90 x K] @ W[K x 128]  + bias  (+ a[r]*vec[c])  | relu |
//               (+ AddSm[r][c]) (+ AddGl[r][c])
// thread map: cg = tid&31 -> 4 consecutive cols; rg = tid>>5 -> 6 rows
// W row stride is 128 floats; W loads double-buffer prefetched.
template<int K, bool RELU, bool RANK1, bool ADDSM, bool ADDGL, bool TROUT>
__device__ __forceinline__ void gemm_stage(
    const float* __restrict__ S, int ldS,
    const float* __restrict__ W,
    const float* __restrict__ bias,
    const float* __restrict__ r1vec,        // global [128]
    const float* __restrict__ avals,        // smem a[90]
    const float* __restrict__ AddSm,        // smem  [90][128]
    const float* __restrict__ AddGl,        // global[90][128]
    float* __restrict__ outR,               // row-major out (stride HD or Y_LD)
    float* __restrict__ outT)               // TROUT: Yt (stride YT_LD)
{
    const int tid = threadIdx.x;
    const int cg = tid & 31;
    const int rg = tid >> 5;
    const int c0 = cg << 2;
    const int r0 = rg * RPG;

    float4 bz = make_float4(0.f, 0.f, 0.f, 0.f);
    if (bias) bz = *(const float4*)(bias + c0);

    u64 acc[RPG][2];
#pragma unroll
    for (int r = 0; r < RPG; ++r) {
        acc[r][0] = pack2(bz.x, bz.y);
        acc[r][1] = pack2(bz.z, bz.w);
    }

    // clamped per-row base pointers (rows >= 90 compute garbage, stay in-bounds)
    const float* srow[RPG];
#pragma unroll
    for (int r = 0; r < RPG; ++r) {
        int rr = r0 + r; if (rr > NN - 1) rr = NN - 1;
        srow[r] = S + rr * ldS;
    }

    const ulonglong2* Wp = (const ulonglong2*)W + cg;   // row stride = 32 ull2

    constexpr int NITER = K / 4;
    constexpr int K4 = NITER * 4;

    ulonglong2 wv[2][4];
#pragma unroll
    for (int i = 0; i < 4; ++i) wv[0][i] = Wp[i * (HD / 4)];

#pragma unroll 2
    for (int it = 0; it < NITER; ++it) {
        const int k = it * 4;
        const int cur = it & 1;
        const int nxt = cur ^ 1;
        if (it + 1 < NITER) {
#pragma unroll
            for (int i = 0; i < 4; ++i)
                wv[nxt][i] = Wp[(k + 4 + i) * (HD / 4)];
        }
        float4 s4[RPG];
#pragma unroll
        for (int r = 0; r < RPG; ++r)
            s4[r] = *(const float4*)(srow[r] + k);
#pragma unroll
        for (int i = 0; i < 4; ++i) {
#pragma unroll
            for (int r = 0; r < RPG; ++r) {
                float s = ((const float*)&s4[r])[i];
                u64 ss = pack2(s, s);
                fma2(acc[r][0], ss, wv[cur][i].x);
                fma2(acc[r][1], ss, wv[cur][i].y);
            }
        }
    }
    // scalar tail (K=90 -> k=88,89)
#pragma unroll
    for (int k = K4; k < K; ++k) {
        ulonglong2 wvt = Wp[k * (HD / 4)];
#pragma unroll
        for (int r = 0; r < RPG; ++r) {
            float s = srow[r][k];
            u64 ss = pack2(s, s);
            fma2(acc[r][0], ss, wvt.x);
            fma2(acc[r][1], ss, wvt.y);
        }
    }

    float4 r1v = make_float4(0.f, 0.f, 0.f, 0.f);
    if (RANK1) r1v = *(const float4*)(r1vec + c0);

#pragma unroll
    for (int r = 0; r < RPG; ++r) {
        int rr = r0 + r;
        if (rr < NN) {
            float2 p0 = unpack2(acc[r][0]);
            float2 p1 = unpack2(acc[r][1]);
            float v0 = p0.x, v1 = p0.y, v2 = p1.x, v3 = p1.y;
            if (RANK1) {
                float av = avals[rr];
                v0 = fmaf(av, r1v.x, v0); v1 = fmaf(av, r1v.y, v1);
                v2 = fmaf(av, r1v.z, v2); v3 = fmaf(av, r1v.w, v3);
            }
            if (RELU) {
                v0 = fmaxf(v0, 0.f); v1 = fmaxf(v1, 0.f);
                v2 = fmaxf(v2, 0.f); v3 = fmaxf(v3, 0.f);
            }
            if (ADDSM) {
                float4 mv = *(const float4*)(AddSm + rr * HD + c0);
                v0 += mv.x; v1 += mv.y; v2 += mv.z; v3 += mv.w;
            }
            if (ADDGL) {
                float4 gv = *(const float4*)(AddGl + rr * HD + c0);
                v0 += gv.x; v1 += gv.y; v2 += gv.z; v3 += gv.w;
            }
            if (TROUT) {
                outT[(c0 + 0) * YT_LD + rr] = v0;
                outT[(c0 + 1) * YT_LD + rr] = v1;
                outT[(c0 + 2) * YT_LD + rr] = v2;
                outT[(c0 + 3) * YT_LD + rr] = v3;
                *(float4*)(outR + rr * Y_LD + c0) = make_float4(v0, v1, v2, v3);
            } else {
                *(float4*)(outR + rr * HD + c0) = make_float4(v0, v1, v2, v3);
            }
        }
    }
}

__global__ void __launch_bounds__(NTHREADS, 1) graphcnn_kernel(
    const float* __restrict__ adj,
    const float* __restrict__ W2g,
    const float* __restrict__ b1g,
    float* __restrict__ out)
{
    extern __shared__ float sm[];
    const int b = blockIdx.x;
    const int tid = threadIdx.x;

    // load adjacency into padded [90 x 92] smem tile
    {
        const float* ag = adj + (size_t)b * (NN * NN);
#pragma unroll
        for (int i = tid; i < NN * NN; i += NTHREADS) {
            int r = i / NN;
            int c = i - r * NN;
            sm[OFF_A + r * A_LD + c] = ag[i];
        }
    }
    __syncthreads();

    // a = rowsums of A
    if (tid < NN) {
        const float* ar = sm + OFF_A + tid * A_LD;
        float s = 0.f;
#pragma unroll 10
        for (int k = 0; k < NN; ++k) s += ar[k];
        sm[OFF_AS + tid] = s;
    }

    // G1: B1 = A @ V1
    gemm_stage<NN, false, false, false, false, false>(
        sm + OFF_A, A_LD, g_V1, nullptr, nullptr, nullptr, nullptr, nullptr,
        sm + OFF_B1, nullptr);
    __syncthreads();

    // G2: R3 = relu(A @ B1 + a v1^T + 1 b1^T)
    gemm_stage<NN, true, true, false, false, false>(
        sm + OFF_A, A_LD, sm + OFF_B1, b1g, g_v1, sm + OFF_AS, nullptr, nullptr,
        sm + OFF_B2, nullptr);
    __syncthreads();

    // G3: M2 = R3 @ W2
    gemm_stage<HD, false, false, false, false, false>(
        sm + OFF_B2, HD, W2g, nullptr, nullptr, nullptr, nullptr, nullptr,
        sm + OFF_B1, nullptr);
    __syncthreads();

    // G4: C = A @ P + M2 + Q
    gemm_stage<NN, false, false, true, true, false>(
        sm + OFF_A, A_LD, g_P, nullptr, nullptr, nullptr, sm + OFF_B1, g_Q,
        sm + OFF_B2, nullptr);
    __syncthreads();

    // G5: Y = relu(A @ C + a p^T + 1 q^T)  -> Y row-major + Yt
    gemm_stage<NN, true, true, false, false, true>(
        sm + OFF_A, A_LD, sm + OFF_B2, g_q, g_p, sm + OFF_AS, nullptr, nullptr,
        sm + OFF_Y, sm + OFF_YT);
    __syncthreads();

    // G6: Z[i][j] = sum_c Y[i][c] * Yt[c][j]
    const int lane = tid & 31;
    const int ig = tid >> 5;
    const int i0 = ig * RPG;

    const float* yirow[RPG];
#pragma unroll
    for (int r = 0; r < RPG; ++r) {
        int ii = i0 + r; if (ii > NN - 1) ii = NN - 1;
        yirow[r] = sm + OFF_Y + ii * Y_LD;
    }

    u64 accp[RPG];                      // packed (j = lane, j = lane+32)
    float accs[RPG];                    // j = lane+64 (only lanes 0..25 valid)
#pragma unroll
    for (int r = 0; r < RPG; ++r) { accp[r] = 0ull; accs[r] = 0.f; }

    const bool has_j2 = (lane + 64) < NN;
#pragma unroll 1
    for (int c = 0; c < HD; c += 4) {
        float4 yi4[RPG];
#pragma unroll
        for (int r = 0; r < RPG; ++r)
            yi4[r] = *(const float4*)(yirow[r] + c);     // broadcast, 1 phase
#pragma unroll
        for (int cc = 0; cc < 4; ++cc) {
            const float* yr = sm + OFF_YT + (c + cc) * YT_LD;
            float yj0 = yr[lane];
            float yj1 = yr[lane + 32];
            float yj2 = has_j2 ? yr[lane + 64] : 0.f;
            u64 yj01 = pack2(yj0, yj1);
#pragma unroll
            for (int r = 0; r < RPG; ++r) {
                float yi = ((const float*)&yi4[r])[cc];
                fma2(accp[r], pack2(yi, yi), yj01);
                accs[r] = fmaf(yi, yj2, accs[r]);
            }
        }
    }

    float* ob = out + (size_t)b * (NN * NN);
#pragma unroll
    for (int r = 0; r < RPG; ++r) {
        int ii = i0 + r;
        if (ii < NN) {
            float2 pj = unpack2(accp[r]);
            ob[ii * NN + lane]      = pj.x;
            ob[ii * NN + lane + 32] = pj.y;
            if (has_j2) ob[ii * NN + lane + 64] = accs[r];
        }
    }
}

extern "C" void kernel_launch(void* const* d_in, const int* in_sizes, int n_in,
                              void* d_out, int out_size) {
    const float* adj = (const float*)d_in[0];
    const float* W0  = (const float*)d_in[1];
    const float* b0  = (const float*)d_in[2];
    const float* W1  = (const float*)d_in[3];
    const float* b1  = (const float*)d_in[4];
    const float* W2  = (const float*)d_in[5];
    const float* b2  = (const float*)d_in[6];
    const float* Wr1 = (const float*)d_in[7];
    const float* br1 = (const float*)d_in[8];
    const float* Wr2 = (const float*)d_in[9];
    const float* br2 = (const float*)d_in[10];
    float* out = (float*)d_out;

    const int B = in_sizes[0] / (NN * NN);
    const size_t smem = SMEM_FLOATS * sizeof(float);   // 219,776 B

    pre1_kernel<<<4, 256>>>(W0, Wr1, W1, b0, br1);
    pre2_kernel<<<4, 256>>>(W2, Wr2, b2, br2);

    cudaFuncSetAttribute(graphcnn_kernel,
                         cudaFuncAttributeMaxDynamicSharedMemorySize, (int)smem);
    graphcnn_kernel<<<B, NTHREADS, smem>>>(adj, W2, b1, out);
}

// round 8
// speedup vs baseline: 1.9793x; 1.0614x over previous
#include <cuda_runtime.h>

typedef unsigned long long u64;

#define NN 90
#define HD 128
#define NTHREADS 480     // 15 warps x 6 rows = exactly 90 rows
#define RPG 6
#define ZS_LD 92

// smem layout (float offsets)
#define A_LD 92          // 90-float rows padded to 92 for 16B alignment
#define OFF_A  0         // 90*92  = 8280   (A, later Zs 90x92)
#define OFF_AS 8280      // a[90] rowsums (pad to 96)
#define OFF_B1 8376      // 90*128 = 11520
#define OFF_B2 19896     // 90*128 = 11520
#define OFF_Y  31416     // 90*132 = 11880 (Y row-major, padded)
#define OFF_YT 43296     // 128*91 = 11648 (Y transposed)
#define SMEM_FLOATS 54944
#define Y_LD 132
#define YT_LD 91

// ---------------- precomputed weight products (device scratch) --------------
__device__ __align__(16) float g_U1[NN * HD];   // W0 @ Wr1
__device__ __align__(16) float g_V1[NN * HD];   // W0 @ W1
__device__ __align__(16) float g_P [NN * HD];   // U1 @ W2
__device__ __align__(16) float g_Q [NN * HD];   // U1 @ Wr2
__device__ __align__(16) float g_u1[HD];        // Wr1^T b0 + br1
__device__ __align__(16) float g_v1[HD];        // W1^T b0
__device__ __align__(16) float g_p [HD];        // W2^T u1
__device__ __align__(16) float g_q [HD];        // Wr2^T u1 + b2 + br2

// one block per output row: out[i,:] = src_row @ M (+addv)
__global__ void pre1_kernel(const float* __restrict__ W0,
                            const float* __restrict__ Wr1,
                            const float* __restrict__ W1,
                            const float* __restrict__ b0,
                            const float* __restrict__ br1)
{
    __shared__ float s[HD];
    const int m = blockIdx.x / (NN + 1);    // 0 -> U1/u1 (Wr1), 1 -> V1/v1 (W1)
    const int i = blockIdx.x % (NN + 1);
    const int t = threadIdx.x;
    const float* M = m ? W1 : Wr1;
    const float* src = (i < NN) ? (W0 + i * HD) : b0;
    s[t] = src[t];
    __syncthreads();
    float acc = 0.f;
#pragma unroll 8
    for (int k = 0; k < HD; ++k) acc = fmaf(s[k], M[k * HD + t], acc);
    if (i < NN) {
        (m ? g_V1 : g_U1)[i * HD + t] = acc;
    } else {
        if (m) g_v1[t] = acc;
        else   g_u1[t] = acc + br1[t];
    }
}

__global__ void pre2_kernel(const float* __restrict__ W2,
                            const float* __restrict__ Wr2,
                            const float* __restrict__ b2,
                            const float* __restrict__ br2)
{
    __shared__ float s[HD];
    const int m = blockIdx.x / (NN + 1);    // 0 -> P/p (W2), 1 -> Q/q (Wr2)
    const int i = blockIdx.x % (NN + 1);
    const int t = threadIdx.x;
    const float* M = m ? Wr2 : W2;
    const float* src = (i < NN) ? (g_U1 + i * HD) : g_u1;
    s[t] = src[t];
    __syncthreads();
    float acc = 0.f;
#pragma unroll 8
    for (int k = 0; k < HD; ++k) acc = fmaf(s[k], M[k * HD + t], acc);
    if (i < NN) {
        (m ? g_Q : g_P)[i * HD + t] = acc;
    } else {
        if (m) g_q[t] = acc + b2[t] + br2[t];
        else   g_p[t] = acc;
    }
}

// ---------------------------- packed fp32x2 helpers -------------------------
__device__ __forceinline__ u64 pack2(float a, float b) {
    u64 r; asm("mov.b64 %0, {%1, %2};" : "=l"(r) : "f"(a), "f"(b)); return r;
}
__device__ __forceinline__ void fma2(u64& d, u64 a, u64 b) {
    asm("fma.rn.f32x2 %0, %1, %2, %0;" : "+l"(d) : "l"(a), "l"(b));
}
__device__ __forceinline__ float2 unpack2(u64 v) {
    float lo, hi; asm("mov.b64 {%0, %1}, %2;" : "=f"(lo), "=f"(hi) : "l"(v));
    return make_float2(lo, hi);
}

// C[90 x 128] = S[90 x K] @ W[K x 128]; epilogue controlled via nullable ptrs
// thread map: cg = tid&31 -> 4 consecutive cols; warp covers rows [r0, r0+6)
template<int K>
__device__ __forceinline__ void gemm_stage(
    const float* __restrict__ S, int ldS,
    const float* __restrict__ W,
    const float* __restrict__ bias,        // nullable
    const float* __restrict__ r1vec,       // nullable: + avals[r]*r1vec[c]
    const float* __restrict__ avals,
    bool relu,
    const float* __restrict__ AddSm,       // nullable: + AddSm[r][c] (stride HD)
    const float* __restrict__ AddGl,       // nullable: + AddGl[r][c] (stride HD)
    float* __restrict__ outR, int ldOutR,  // row-major out
    float* __restrict__ outT,              // nullable: also transpose (YT_LD)
    int r0)
{
    const int tid = threadIdx.x;
    const int cg = tid & 31;
    const int c0 = cg << 2;

    float4 bz = make_float4(0.f, 0.f, 0.f, 0.f);
    if (bias) bz = *(const float4*)(bias + c0);

    u64 acc[RPG][2];
#pragma unroll
    for (int r = 0; r < RPG; ++r) {
        acc[r][0] = pack2(bz.x, bz.y);
        acc[r][1] = pack2(bz.z, bz.w);
    }

    const float* srow[RPG];
#pragma unroll
    for (int r = 0; r < RPG; ++r) srow[r] = S + (r0 + r) * ldS;

    const ulonglong2* Wp = (const ulonglong2*)W + cg;   // row stride = 32 ull2

    constexpr int NITER = K / 4;
    constexpr int K4 = NITER * 4;

    ulonglong2 wv[2][4];
#pragma unroll
    for (int i = 0; i < 4; ++i) wv[0][i] = Wp[i * (HD / 4)];

#pragma unroll 2
    for (int it = 0; it < NITER; ++it) {
        const int k = it * 4;
        const int cur = it & 1;
        const int nxt = cur ^ 1;
        if (it + 1 < NITER) {
#pragma unroll
            for (int i = 0; i < 4; ++i)
                wv[nxt][i] = Wp[(k + 4 + i) * (HD / 4)];
        }
        float4 s4[RPG];
#pragma unroll
        for (int r = 0; r < RPG; ++r)
            s4[r] = *(const float4*)(srow[r] + k);
#pragma unroll
        for (int i = 0; i < 4; ++i) {
#pragma unroll
            for (int r = 0; r < RPG; ++r) {
                float s = ((const float*)&s4[r])[i];
                u64 ss = pack2(s, s);
                fma2(acc[r][0], ss, wv[cur][i].x);
                fma2(acc[r][1], ss, wv[cur][i].y);
            }
        }
    }
#pragma unroll
    for (int k = K4; k < K; ++k) {
        ulonglong2 wvt = Wp[k * (HD / 4)];
#pragma unroll
        for (int r = 0; r < RPG; ++r) {
            float s = srow[r][k];
            u64 ss = pack2(s, s);
            fma2(acc[r][0], ss, wvt.x);
            fma2(acc[r][1], ss, wvt.y);
        }
    }

    float4 r1v = make_float4(0.f, 0.f, 0.f, 0.f);
    if (r1vec) r1v = *(const float4*)(r1vec + c0);

#pragma unroll
    for (int r = 0; r < RPG; ++r) {
        const int rr = r0 + r;
        float2 p0 = unpack2(acc[r][0]);
        float2 p1 = unpack2(acc[r][1]);
        float v0 = p0.x, v1 = p0.y, v2 = p1.x, v3 = p1.y;
        if (r1vec) {
            float av = avals[rr];
            v0 = fmaf(av, r1v.x, v0); v1 = fmaf(av, r1v.y, v1);
            v2 = fmaf(av, r1v.z, v2); v3 = fmaf(av, r1v.w, v3);
        }
        if (relu) {
            v0 = fmaxf(v0, 0.f); v1 = fmaxf(v1, 0.f);
            v2 = fmaxf(v2, 0.f); v3 = fmaxf(v3, 0.f);
        }
        if (AddSm) {
            float4 mv = *(const float4*)(AddSm + rr * HD + c0);
            v0 += mv.x; v1 += mv.y; v2 += mv.z; v3 += mv.w;
        }
        if (AddGl) {
            float4 gv = *(const float4*)(AddGl + rr * HD + c0);
            v0 += gv.x; v1 += gv.y; v2 += gv.z; v3 += gv.w;
        }
        if (outT) {
            outT[(c0 + 0) * YT_LD + rr] = v0;
            outT[(c0 + 1) * YT_LD + rr] = v1;
            outT[(c0 + 2) * YT_LD + rr] = v2;
            outT[(c0 + 3) * YT_LD + rr] = v3;
        }
        *(float4*)(outR + rr * ldOutR + c0) = make_float4(v0, v1, v2, v3);
    }
}

// Z stage: rows [r0, r0+6), j-blocks >= NB only (lower blocks mirrored later)
template<int NB>
__device__ __forceinline__ void z_stage(const float* __restrict__ sm,
                                        float* __restrict__ Zs,
                                        int r0, int lane)
{
    const float* Yb  = sm + OFF_Y;
    const float* YTb = sm + OFF_YT;
    const float* yirow[RPG];
#pragma unroll
    for (int r = 0; r < RPG; ++r) yirow[r] = Yb + (r0 + r) * Y_LD;

    const bool has_j2 = lane < (NN - 64);   // lane+64 < 90

    u64 accp[RPG];
    float accs[RPG];
#pragma unroll
    for (int r = 0; r < RPG; ++r) { accp[r] = 0ull; accs[r] = 0.f; }

#pragma unroll 1
    for (int c = 0; c < HD; c += 4) {
        float4 yi4[RPG];
#pragma unroll
        for (int r = 0; r < RPG; ++r)
            yi4[r] = *(const float4*)(yirow[r] + c);     // broadcast
#pragma unroll
        for (int cc = 0; cc < 4; ++cc) {
            const float* yr = YTb + (c + cc) * YT_LD;
            float yj2 = has_j2 ? yr[lane + 64] : 0.f;
            if (NB == 0) {
                u64 yj01 = pack2(yr[lane], yr[lane + 32]);
#pragma unroll
                for (int r = 0; r < RPG; ++r) {
                    float yi = ((const float*)&yi4[r])[cc];
                    fma2(accp[r], pack2(yi, yi), yj01);
                    accs[r] = fmaf(yi, yj2, accs[r]);
                }
            } else if (NB == 1) {
                u64 yj12 = pack2(yr[lane + 32], yj2);
#pragma unroll
                for (int r = 0; r < RPG; ++r) {
                    float yi = ((const float*)&yi4[r])[cc];
                    fma2(accp[r], pack2(yi, yi), yj12);
                }
            } else {
#pragma unroll
                for (int r = 0; r < RPG; ++r) {
                    float yi = ((const float*)&yi4[r])[cc];
                    accs[r] = fmaf(yi, yj2, accs[r]);
                }
            }
        }
    }

#pragma unroll
    for (int r = 0; r < RPG; ++r) {
        const int i = r0 + r;
        float* zr = Zs + i * ZS_LD;
        if (NB == 0) {
            float2 pj = unpack2(accp[r]);
            zr[lane]      = pj.x;
            zr[lane + 32] = pj.y;
            if (has_j2) zr[lane + 64] = accs[r];
        } else if (NB == 1) {
            float2 pj = unpack2(accp[r]);
            zr[lane + 32] = pj.x;
            if (has_j2) zr[lane + 64] = pj.y;
        } else {
            if (has_j2) zr[lane + 64] = accs[r];
        }
    }
}

__global__ void __launch_bounds__(NTHREADS, 1) graphcnn_kernel(
    const float* __restrict__ adj,
    const float* __restrict__ W2g,
    const float* __restrict__ b1g,
    float* __restrict__ out)
{
    extern __shared__ float sm[];
    const int b = blockIdx.x;
    const int tid = threadIdx.x;
    const int w = tid >> 5;
    const int lane = tid & 31;
    const int r0 = RPG * w;                  // 15 warps x 6 rows = 90 exactly

    // load adjacency into padded [90 x 92] smem tile
    {
        const float* ag = adj + (size_t)b * (NN * NN);
#pragma unroll
        for (int i = tid; i < NN * NN; i += NTHREADS) {
            int r = i / NN;
            int c = i - r * NN;
            sm[OFF_A + r * A_LD + c] = ag[i];
        }
    }
    __syncthreads();

    // a = rowsums of A
    if (tid < NN) {
        const float* ar = sm + OFF_A + tid * A_LD;
        float s = 0.f;
#pragma unroll 10
        for (int k = 0; k < NN; ++k) s += ar[k];
        sm[OFF_AS + tid] = s;
    }

    // G1: B1 = A @ V1
    gemm_stage<NN>(sm + OFF_A, A_LD, g_V1, nullptr, nullptr, nullptr, false,
                   nullptr, nullptr, sm + OFF_B1, HD, nullptr, r0);
    __syncthreads();

    // G2: R3 = relu(A @ B1 + a v1^T + 1 b1^T)
    gemm_stage<NN>(sm + OFF_A, A_LD, sm + OFF_B1, b1g, g_v1, sm + OFF_AS, true,
                   nullptr, nullptr, sm + OFF_B2, HD, nullptr, r0);
    __syncthreads();

    // G3: M2 = R3 @ W2
    gemm_stage<HD>(sm + OFF_B2, HD, W2g, nullptr, nullptr, nullptr, false,
                   nullptr, nullptr, sm + OFF_B1, HD, nullptr, r0);
    __syncthreads();

    // G4: C = A @ P + M2 + Q
    gemm_stage<NN>(sm + OFF_A, A_LD, g_P, nullptr, nullptr, nullptr, false,
                   sm + OFF_B1, g_Q, sm + OFF_B2, HD, nullptr, r0);
    __syncthreads();

    // G5: Y = relu(A @ C + a p^T + 1 q^T)  -> Y (Y_LD) + YT
    gemm_stage<NN>(sm + OFF_A, A_LD, sm + OFF_B2, g_q, g_p, sm + OFF_AS, true,
                   nullptr, nullptr, sm + OFF_Y, Y_LD, sm + OFF_YT, r0);
    __syncthreads();

    // G6: Zs[i][j] = sum_c Y[i][c] * Yt[c][j], skipping j-blocks below diag
    // warps 0-5 (rows 0-35):   NB=0 (all blocks)
    // warps 6-10 (rows 36-65): NB=1 (blocks 1,2)
    // warps 11-14 (rows 66-89):NB=2 (block 2)
    float* Zs = sm + OFF_A;                    // A is dead; 90*92 fits exactly
    if (r0 < 32)      z_stage<0>(sm, Zs, r0, lane);
    else if (r0 < 64) z_stage<1>(sm, Zs, r0, lane);
    else              z_stage<2>(sm, Zs, r0, lane);
    __syncthreads();

    // mirror + writeout: skipped (i,j) come from Zs[j][i]
    float* ob = out + (size_t)b * (NN * NN);
#pragma unroll
    for (int idx = tid; idx < NN * NN; idx += NTHREADS) {
        int i = idx / NN;
        int j = idx - i * NN;
        int rs = (i / RPG) * RPG;              // owning warp's r0
        int nbi = (rs >= 64) ? 2 : (rs >= 32 ? 1 : 0);
        bool avail = (j >> 5) >= nbi;
        ob[idx] = avail ? Zs[i * ZS_LD + j] : Zs[j * ZS_LD + i];
    }
}

extern "C" void kernel_launch(void* const* d_in, const int* in_sizes, int n_in,
                              void* d_out, int out_size) {
    const float* adj = (const float*)d_in[0];
    const float* W0  = (const float*)d_in[1];
    const float* b0  = (const float*)d_in[2];
    const float* W1  = (const float*)d_in[3];
    const float* b1  = (const float*)d_in[4];
    const float* W2  = (const float*)d_in[5];
    const float* b2  = (const float*)d_in[6];
    const float* Wr1 = (const float*)d_in[7];
    const float* br1 = (const float*)d_in[8];
    const float* Wr2 = (const float*)d_in[9];
    const float* br2 = (const float*)d_in[10];
    float* out = (float*)d_out;

    const int B = in_sizes[0] / (NN * NN);
    const size_t smem = SMEM_FLOATS * sizeof(float);   // 219,776 B

    pre1_kernel<<<2 * (NN + 1), HD>>>(W0, Wr1, W1, b0, br1);
    pre2_kernel<<<2 * (NN + 1), HD>>>(W2, Wr2, b2, br2);

    cudaFuncSetAttribute(graphcnn_kernel,
                         cudaFuncAttributeMaxDynamicSharedMemorySize, (int)smem);
    graphcnn_kernel<<<B, NTHREADS, smem>>>(adj, W2, b1, out);
}

// round 9
// speedup vs baseline: 1.9826x; 1.0016x over previous
#include <cuda_runtime.h>

typedef unsigned long long u64;

#define NN 90
#define HD 128
#define NTHREADS 480     // 15 warps x 6 rows = exactly 90 rows
#define RPG 6
#define ZS_LD 92

// smem layout (float offsets)
#define A_LD 92          // 90-float rows padded to 92 for 16B alignment
#define OFF_A  0         // 90*92  = 8280   (A, later Zs 90x92)
#define OFF_AS 8280      // a[90] rowsums (pad to 96)
#define OFF_B1 8376      // 90*128 = 11520
#define OFF_B2 19896     // 90*128 = 11520
#define OFF_Y  31416     // 90*132 = 11880 (Y row-major, padded)
#define OFF_YT 43296     // 128*91 = 11648 (Y transposed)
#define SMEM_FLOATS 54944
#define Y_LD 132
#define YT_LD 91

// ---------------- precomputed weight products (device scratch) --------------
__device__ __align__(16) float g_U1[NN * HD];   // W0 @ Wr1
__device__ __align__(16) float g_V1[NN * HD];   // W0 @ W1
__device__ __align__(16) float g_P [NN * HD];   // U1 @ W2
__device__ __align__(16) float g_Q [NN * HD];   // U1 @ Wr2
__device__ __align__(16) float g_u1[HD];        // Wr1^T b0 + br1
__device__ __align__(16) float g_v1[HD];        // W1^T b0
__device__ __align__(16) float g_p [HD];        // W2^T u1
__device__ __align__(16) float g_q [HD];        // Wr2^T u1 + b2 + br2

// one block per output row: out[i,:] = src_row @ M (+addv)
__global__ void pre1_kernel(const float* __restrict__ W0,
                            const float* __restrict__ Wr1,
                            const float* __restrict__ W1,
                            const float* __restrict__ b0,
                            const float* __restrict__ br1)
{
    __shared__ float s[HD];
    const int m = blockIdx.x / (NN + 1);    // 0 -> U1/u1 (Wr1), 1 -> V1/v1 (W1)
    const int i = blockIdx.x % (NN + 1);
    const int t = threadIdx.x;
    const float* M = m ? W1 : Wr1;
    const float* src = (i < NN) ? (W0 + i * HD) : b0;
    s[t] = src[t];
    __syncthreads();
    float acc = 0.f;
#pragma unroll 8
    for (int k = 0; k < HD; ++k) acc = fmaf(s[k], M[k * HD + t], acc);
    if (i < NN) {
        (m ? g_V1 : g_U1)[i * HD + t] = acc;
    } else {
        if (m) g_v1[t] = acc;
        else   g_u1[t] = acc + br1[t];
    }
}

__global__ void pre2_kernel(const float* __restrict__ W2,
                            const float* __restrict__ Wr2,
                            const float* __restrict__ b2,
                            const float* __restrict__ br2)
{
    __shared__ float s[HD];
    const int m = blockIdx.x / (NN + 1);    // 0 -> P/p (W2), 1 -> Q/q (Wr2)
    const int i = blockIdx.x % (NN + 1);
    const int t = threadIdx.x;
    const float* M = m ? Wr2 : W2;
    const float* src = (i < NN) ? (g_U1 + i * HD) : g_u1;
    s[t] = src[t];
    __syncthreads();
    float acc = 0.f;
#pragma unroll 8
    for (int k = 0; k < HD; ++k) acc = fmaf(s[k], M[k * HD + t], acc);
    if (i < NN) {
        (m ? g_Q : g_P)[i * HD + t] = acc;
    } else {
        if (m) g_q[t] = acc + b2[t] + br2[t];
        else   g_p[t] = acc;
    }
}

// ---------------------------- packed fp32x2 helpers -------------------------
__device__ __forceinline__ u64 pack2(float a, float b) {
    u64 r; asm("mov.b64 %0, {%1, %2};" : "=l"(r) : "f"(a), "f"(b)); return r;
}
__device__ __forceinline__ void fma2(u64& d, u64 a, u64 b) {
    asm("fma.rn.f32x2 %0, %1, %2, %0;" : "+l"(d) : "l"(a), "l"(b));
}
__device__ __forceinline__ float2 unpack2(u64 v) {
    float lo, hi; asm("mov.b64 {%0, %1}, %2;" : "=f"(lo), "=f"(hi) : "l"(v));
    return make_float2(lo, hi);
}

// C[90 x 128] = S[90 x K] @ W[K x 128]; epilogue controlled via nullable ptrs
// thread map: cg = tid&31 -> 4 consecutive cols; warp covers rows [r0, r0+6)
template<int K>
__device__ __forceinline__ void gemm_stage(
    const float* __restrict__ S, int ldS,
    const float* __restrict__ W,
    const float* __restrict__ bias,        // nullable
    const float* __restrict__ r1vec,       // nullable: + avals[r]*r1vec[c]
    const float* __restrict__ avals,
    bool relu,
    const float* __restrict__ AddSm,       // nullable: + AddSm[r][c] (stride HD)
    const float* __restrict__ AddGl,       // nullable: + AddGl[r][c] (stride HD)
    float* __restrict__ outR, int ldOutR,  // row-major out
    float* __restrict__ outT,              // nullable: also transpose (YT_LD)
    int r0)
{
    const int tid = threadIdx.x;
    const int cg = tid & 31;
    const int c0 = cg << 2;

    float4 bz = make_float4(0.f, 0.f, 0.f, 0.f);
    if (bias) bz = *(const float4*)(bias + c0);

    u64 acc[RPG][2];
#pragma unroll
    for (int r = 0; r < RPG; ++r) {
        acc[r][0] = pack2(bz.x, bz.y);
        acc[r][1] = pack2(bz.z, bz.w);
    }

    const float* srow[RPG];
#pragma unroll
    for (int r = 0; r < RPG; ++r) srow[r] = S + (r0 + r) * ldS;

    const ulonglong2* Wp = (const ulonglong2*)W + cg;   // row stride = 32 ull2

    constexpr int NITER = K / 4;
    constexpr int K4 = NITER * 4;

    ulonglong2 wv[2][4];
#pragma unroll
    for (int i = 0; i < 4; ++i) wv[0][i] = Wp[i * (HD / 4)];

#pragma unroll 2
    for (int it = 0; it < NITER; ++it) {
        const int k = it * 4;
        const int cur = it & 1;
        const int nxt = cur ^ 1;
        if (it + 1 < NITER) {
#pragma unroll
            for (int i = 0; i < 4; ++i)
                wv[nxt][i] = Wp[(k + 4 + i) * (HD / 4)];
        }
        float4 s4[RPG];
#pragma unroll
        for (int r = 0; r < RPG; ++r)
            s4[r] = *(const float4*)(srow[r] + k);
#pragma unroll
        for (int i = 0; i < 4; ++i) {
#pragma unroll
            for (int r = 0; r < RPG; ++r) {
                float s = ((const float*)&s4[r])[i];
                u64 ss = pack2(s, s);
                fma2(acc[r][0], ss, wv[cur][i].x);
                fma2(acc[r][1], ss, wv[cur][i].y);
            }
        }
    }
#pragma unroll
    for (int k = K4; k < K; ++k) {
        ulonglong2 wvt = Wp[k * (HD / 4)];
#pragma unroll
        for (int r = 0; r < RPG; ++r) {
            float s = srow[r][k];
            u64 ss = pack2(s, s);
            fma2(acc[r][0], ss, wvt.x);
            fma2(acc[r][1], ss, wvt.y);
        }
    }

    float4 r1v = make_float4(0.f, 0.f, 0.f, 0.f);
    if (r1vec) r1v = *(const float4*)(r1vec + c0);

#pragma unroll
    for (int r = 0; r < RPG; ++r) {
        const int rr = r0 + r;
        float2 p0 = unpack2(acc[r][0]);
        float2 p1 = unpack2(acc[r][1]);
        float v0 = p0.x, v1 = p0.y, v2 = p1.x, v3 = p1.y;
        if (r1vec) {
            float av = avals[rr];
            v0 = fmaf(av, r1v.x, v0); v1 = fmaf(av, r1v.y, v1);
            v2 = fmaf(av, r1v.z, v2); v3 = fmaf(av, r1v.w, v3);
        }
        if (relu) {
            v0 = fmaxf(v0, 0.f); v1 = fmaxf(v1, 0.f);
            v2 = fmaxf(v2, 0.f); v3 = fmaxf(v3, 0.f);
        }
        if (AddSm) {
            float4 mv = *(const float4*)(AddSm + rr * HD + c0);
            v0 += mv.x; v1 += mv.y; v2 += mv.z; v3 += mv.w;
        }
        if (AddGl) {
            float4 gv = *(const float4*)(AddGl + rr * HD + c0);
            v0 += gv.x; v1 += gv.y; v2 += gv.z; v3 += gv.w;
        }
        if (outT) {
            outT[(c0 + 0) * YT_LD + rr] = v0;
            outT[(c0 + 1) * YT_LD + rr] = v1;
            outT[(c0 + 2) * YT_LD + rr] = v2;
            outT[(c0 + 3) * YT_LD + rr] = v3;
        }
        *(float4*)(outR + rr * ldOutR + c0) = make_float4(v0, v1, v2, v3);
    }
}

// Z stage: rows [r0, r0+6), j-blocks >= NB only (lower blocks mirrored later)
template<int NB>
__device__ __forceinline__ void z_stage(const float* __restrict__ sm,
                                        float* __restrict__ Zs,
                                        int r0, int lane)
{
    const float* Yb  = sm + OFF_Y;
    const float* YTb = sm + OFF_YT;
    const float* yirow[RPG];
#pragma unroll
    for (int r = 0; r < RPG; ++r) yirow[r] = Yb + (r0 + r) * Y_LD;

    const bool has_j2 = lane < (NN - 64);   // lane+64 < 90

    u64 accp[RPG];
    float accs[RPG];
#pragma unroll
    for (int r = 0; r < RPG; ++r) { accp[r] = 0ull; accs[r] = 0.f; }

#pragma unroll 1
    for (int c = 0; c < HD; c += 4) {
        float4 yi4[RPG];
#pragma unroll
        for (int r = 0; r < RPG; ++r)
            yi4[r] = *(const float4*)(yirow[r] + c);     // broadcast
#pragma unroll
        for (int cc = 0; cc < 4; ++cc) {
            const float* yr = YTb + (c + cc) * YT_LD;
            float yj2 = has_j2 ? yr[lane + 64] : 0.f;
            if (NB == 0) {
                u64 yj01 = pack2(yr[lane], yr[lane + 32]);
#pragma unroll
                for (int r = 0; r < RPG; ++r) {
                    float yi = ((const float*)&yi4[r])[cc];
                    fma2(accp[r], pack2(yi, yi), yj01);
                    accs[r] = fmaf(yi, yj2, accs[r]);
                }
            } else if (NB == 1) {
                u64 yj12 = pack2(yr[lane + 32], yj2);
#pragma unroll
                for (int r = 0; r < RPG; ++r) {
                    float yi = ((const float*)&yi4[r])[cc];
                    fma2(accp[r], pack2(yi, yi), yj12);
                }
            } else {
#pragma unroll
                for (int r = 0; r < RPG; ++r) {
                    float yi = ((const float*)&yi4[r])[cc];
                    accs[r] = fmaf(yi, yj2, accs[r]);
                }
            }
        }
    }

#pragma unroll
    for (int r = 0; r < RPG; ++r) {
        const int i = r0 + r;
        float* zr = Zs + i * ZS_LD;
        if (NB == 0) {
            float2 pj = unpack2(accp[r]);
            zr[lane]      = pj.x;
            zr[lane + 32] = pj.y;
            if (has_j2) zr[lane + 64] = accs[r];
        } else if (NB == 1) {
            float2 pj = unpack2(accp[r]);
            zr[lane + 32] = pj.x;
            if (has_j2) zr[lane + 64] = pj.y;
        } else {
            if (has_j2) zr[lane + 64] = accs[r];
        }
    }
}

__global__ void __launch_bounds__(NTHREADS, 1) graphcnn_kernel(
    const float* __restrict__ adj,
    const float* __restrict__ W2g,
    const float* __restrict__ b1g,
    float* __restrict__ out)
{
    extern __shared__ float sm[];
    const int b = blockIdx.x;
    const int tid = threadIdx.x;
    const int w = tid >> 5;
    const int lane = tid & 31;
    const int r0 = RPG * w;                  // 15 warps x 6 rows = 90 exactly

    // load adjacency into padded [90 x 92] smem tile
    {
        const float* ag = adj + (size_t)b * (NN * NN);
#pragma unroll
        for (int i = tid; i < NN * NN; i += NTHREADS) {
            int r = i / NN;
            int c = i - r * NN;
            sm[OFF_A + r * A_LD + c] = ag[i];
        }
    }
    __syncthreads();

    // a = rowsums of A
    if (tid < NN) {
        const float* ar = sm + OFF_A + tid * A_LD;
        float s = 0.f;
#pragma unroll 10
        for (int k = 0; k < NN; ++k) s += ar[k];
        sm[OFF_AS + tid] = s;
    }

    // G1: B1 = A @ V1
    gemm_stage<NN>(sm + OFF_A, A_LD, g_V1, nullptr, nullptr, nullptr, false,
                   nullptr, nullptr, sm + OFF_B1, HD, nullptr, r0);
    __syncthreads();

    // G2: R3 = relu(A @ B1 + a v1^T + 1 b1^T)
    gemm_stage<NN>(sm + OFF_A, A_LD, sm + OFF_B1, b1g, g_v1, sm + OFF_AS, true,
                   nullptr, nullptr, sm + OFF_B2, HD, nullptr, r0);
    __syncthreads();

    // G3: M2 = R3 @ W2
    gemm_stage<HD>(sm + OFF_B2, HD, W2g, nullptr, nullptr, nullptr, false,
                   nullptr, nullptr, sm + OFF_B1, HD, nullptr, r0);
    __syncthreads();

    // G4: C = A @ P + M2 + Q
    gemm_stage<NN>(sm + OFF_A, A_LD, g_P, nullptr, nullptr, nullptr, false,
                   sm + OFF_B1, g_Q, sm + OFF_B2, HD, nullptr, r0);
    __syncthreads();

    // G5: Y = relu(A @ C + a p^T + 1 q^T)  -> Y (Y_LD) + YT
    gemm_stage<NN>(sm + OFF_A, A_LD, sm + OFF_B2, g_q, g_p, sm + OFF_AS, true,
                   nullptr, nullptr, sm + OFF_Y, Y_LD, sm + OFF_YT, r0);
    __syncthreads();

    // G6: Zs[i][j] = sum_c Y[i][c] * Yt[c][j], skipping j-blocks below diag
    // warps 0-5 (rows 0-35):   NB=0 (all blocks)
    // warps 6-10 (rows 36-65): NB=1 (blocks 1,2)
    // warps 11-14 (rows 66-89):NB=2 (block 2)
    float* Zs = sm + OFF_A;                    // A is dead; 90*92 fits exactly
    if (r0 < 32)      z_stage<0>(sm, Zs, r0, lane);
    else if (r0 < 64) z_stage<1>(sm, Zs, r0, lane);
    else              z_stage<2>(sm, Zs, r0, lane);
    __syncthreads();

    // mirror + writeout: skipped (i,j) come from Zs[j][i]
    float* ob = out + (size_t)b * (NN * NN);
#pragma unroll
    for (int idx = tid; idx < NN * NN; idx += NTHREADS) {
        int i = idx / NN;
        int j = idx - i * NN;
        int rs = (i / RPG) * RPG;              // owning warp's r0
        int nbi = (rs >= 64) ? 2 : (rs >= 32 ? 1 : 0);
        bool avail = (j >> 5) >= nbi;
        ob[idx] = avail ? Zs[i * ZS_LD + j] : Zs[j * ZS_LD + i];
    }
}

extern "C" void kernel_launch(void* const* d_in, const int* in_sizes, int n_in,
                              void* d_out, int out_size) {
    const float* adj = (const float*)d_in[0];
    const float* W0  = (const float*)d_in[1];
    const float* b0  = (const float*)d_in[2];
    const float* W1  = (const float*)d_in[3];
    const float* b1  = (const float*)d_in[4];
    const float* W2  = (const float*)d_in[5];
    const float* b2  = (const float*)d_in[6];
    const float* Wr1 = (const float*)d_in[7];
    const float* br1 = (const float*)d_in[8];
    const float* Wr2 = (const float*)d_in[9];
    const float* br2 = (const float*)d_in[10];
    float* out = (float*)d_out;

    const int B = in_sizes[0] / (NN * NN);
    const size_t smem = SMEM_FLOATS * sizeof(float);   // 219,776 B

    pre1_kernel<<<2 * (NN + 1), HD>>>(W0, Wr1, W1, b0, br1);
    pre2_kernel<<<2 * (NN + 1), HD>>>(W2, Wr2, b2, br2);

    cudaFuncSetAttribute(graphcnn_kernel,
                         cudaFuncAttributeMaxDynamicSharedMemorySize, (int)smem);
    graphcnn_kernel<<<B, NTHREADS, smem>>>(adj, W2, b1, out);
}